// round 8
// baseline (speedup 1.0000x reference)
#include <cuda_runtime.h>

// ResidualEmbedding: per-frame Burg LPC (order 12) residual, sign-modulated embed.
// R8: TWO independent Burg chains per warp (8 frames/warp = 2 sets x (4 frames,
//     8 lanes, 20 samples/lane)). Chain B's FMAs fill chain A's SHFL/div stalls.
//  - Hann window precomputed once per block into shared (same for all frames).
//  - LDG.128/STS.128/LDS.128/STG.128 data movement; zero-propagation invariant.

namespace {

constexpr int FRAME   = 160;
constexpr int ORDER   = 12;
constexpr int NFRAMES = 4096 * 15;       // 61440
constexpr int WPB     = 8;               // warps per block (64 frames/block)
constexpr int THREADS = WPB * 32;
constexpr int ROW     = 176;             // 12 halo + 160 + 4 pad (floats)
constexpr unsigned FULL = 0xffffffffu;

__device__ __forceinline__ float grp_sum(float v) {
#pragma unroll
    for (int o = 4; o > 0; o >>= 1) v += __shfl_xor_sync(FULL, v, o);
    return v;
}

__global__ __launch_bounds__(THREADS, 2) void burg_residual_kernel(
    const int*   __restrict__ bits,
    const float* __restrict__ pcm,
    const float* __restrict__ alpha_p,
    float*       __restrict__ out)
{
    const int warp   = threadIdx.x >> 5;
    const int lane   = threadIdx.x & 31;
    const int frame0 = (blockIdx.x * WPB + warp) * 8;   // exact grid
    const int sub    = lane >> 3;        // frame-in-set
    const int lh     = lane & 7;
    const int jb     = 20 * lh;

    __shared__ float win[FRAME];
    __shared__ float Xs[WPB][8][ROW];

    // ---- Hann window once per block: w[j] = 0.5 - 0.5*cos(2*pi*j/159) ----
    if (threadIdx.x < FRAME)
        win[threadIdx.x] =
            0.5f - 0.5f * __cosf((6.283185307179586f / 159.0f) * (float)threadIdx.x);
    __syncthreads();

    const int frA = frame0 + sub;        // set A frame
    const int frB = frame0 + 4 + sub;    // set B frame
    float* __restrict__ PA = &Xs[warp][sub][0];
    float* __restrict__ PB = &Xs[warp][4 + sub][0];

    // ---- Vectorized loads (both sets) + stash to shared with zero halo ----
    float xA[20], xB[20];
    {
        const float4* sA = (const float4*)(pcm + (long long)frA * FRAME + jb);
        const float4* sB = (const float4*)(pcm + (long long)frB * FRAME + jb);
#pragma unroll
        for (int k = 0; k < 5; ++k) {
            const float4 a = sA[k], b = sB[k];
            xA[4*k]=a.x; xA[4*k+1]=a.y; xA[4*k+2]=a.z; xA[4*k+3]=a.w;
            xB[4*k]=b.x; xB[4*k+1]=b.y; xB[4*k+2]=b.z; xB[4*k+3]=b.w;
        }
        float4* dA = (float4*)(PA + 12 + jb);
        float4* dB = (float4*)(PB + 12 + jb);
#pragma unroll
        for (int k = 0; k < 5; ++k) {
            dA[k] = make_float4(xA[4*k], xA[4*k+1], xA[4*k+2], xA[4*k+3]);
            dB[k] = make_float4(xB[4*k], xB[4*k+1], xB[4*k+2], xB[4*k+3]);
        }
        if (lh < 3) {
            ((float4*)PA)[lh] = make_float4(0.f, 0.f, 0.f, 0.f);
            ((float4*)PB)[lh] = make_float4(0.f, 0.f, 0.f, 0.f);
        }
    }

    // ---- Windowed init for both chains ----
    float fA[20], bA[20], fB[20], bB[20];
    {
        float wv[20];
        const float4* W = (const float4*)(win + jb);
#pragma unroll
        for (int k = 0; k < 5; ++k) {
            const float4 v = W[k];
            wv[4*k]=v.x; wv[4*k+1]=v.y; wv[4*k+2]=v.z; wv[4*k+3]=v.w;
        }
#pragma unroll
        for (int c = 0; c < 20; ++c) { bA[c] = xA[c] * wv[c]; bB[c] = xB[c] * wv[c]; }
    }
#pragma unroll
    for (int c = 0; c < 19; ++c) { fA[c] = bA[c + 1]; fB[c] = bB[c + 1]; }
    {
        const float nA = __shfl_sync(FULL, bA[0], lane + 1);
        const float nB = __shfl_sync(FULL, bB[0], lane + 1);
        fA[19] = (lh == 7) ? 0.f : nA;
        fB[19] = (lh == 7) ? 0.f : nB;
    }
    if (lh == 7) { bA[19] = 0.f; bB[19] = 0.f; }

    float denA, denB;
    {
        float pa0 = 0.f, pa1 = 0.f, pb0 = 0.f, pb1 = 0.f;
#pragma unroll
        for (int c = 0; c < 20; c += 2) {
            pa0 = fmaf(fA[c],   fA[c],   fmaf(bA[c],   bA[c],   pa0));
            pa1 = fmaf(fA[c+1], fA[c+1], fmaf(bA[c+1], bA[c+1], pa1));
            pb0 = fmaf(fB[c],   fB[c],   fmaf(bB[c],   bB[c],   pb0));
            pb1 = fmaf(fB[c+1], fB[c+1], fmaf(bB[c+1], bB[c+1], pb1));
        }
        denA = grp_sum(pa0 + pa1);
        denB = grp_sum(pb0 + pb1);
    }

    float aA[ORDER + 1], aB[ORDER + 1];
    aA[0] = 1.f; aB[0] = 1.f;
#pragma unroll
    for (int k = 1; k <= ORDER; ++k) { aA[k] = 0.f; aB[k] = 0.f; }

    // ---- Burg recursion: both chains interleaved ----
#pragma unroll
    for (int i = 0; i < ORDER; ++i) {
        float pa0 = 0.f, pa1 = 0.f, pb0 = 0.f, pb1 = 0.f;
#pragma unroll
        for (int c = 0; c < 20; c += 2) {
            pa0 = fmaf(fA[c],   bA[c],   pa0);
            pa1 = fmaf(fA[c+1], bA[c+1], pa1);
            pb0 = fmaf(fB[c],   bB[c],   pb0);
            pb1 = fmaf(fB[c+1], bB[c+1], pb1);
        }
        const float sA = grp_sum(pa0 + pa1);
        const float sB = grp_sum(pb0 + pb1);
        const float rA = __fdividef(-2.f * sA, denA);
        const float rB = __fdividef(-2.f * sB, denB);

#pragma unroll
        for (int c = 0; c < 20; ++c) {
            const float foA = fA[c], foB = fB[c];
            fA[c] = fmaf(rA, bA[c], fA[c]);
            bA[c] = fmaf(rA, foA,   bA[c]);
            fB[c] = fmaf(rB, bB[c], fB[c]);
            bB[c] = fmaf(rB, foB,   bB[c]);
        }

        const int jl = 158 - i, Ll = jl / 20, cl = jl % 20;   // compile-time
        const float nA = __shfl_sync(FULL, fA[0], lane + 1);
        const float nB = __shfl_sync(FULL, fB[0], lane + 1);
        const float tA = __shfl_sync(FULL, fA[0], lane & ~7);
        const float tB = __shfl_sync(FULL, fB[0], lane & ~7);
        const float uA = __shfl_sync(FULL, bA[cl], (lane & ~7) | Ll);
        const float uB = __shfl_sync(FULL, bB[cl], (lane & ~7) | Ll);
        denA = (1.f - rA * rA) * denA - uA * uA - tA * tA;
        denB = (1.f - rB * rB) * denB - uB * uB - tB * tB;

#pragma unroll
        for (int c = 0; c < 19; ++c) { fA[c] = fA[c + 1]; fB[c] = fB[c + 1]; }
        fA[19] = (lh == 7) ? 0.f : nA;
        fB[19] = (lh == 7) ? 0.f : nB;
        if (lh == Ll) { bA[cl] = 0.f; bB[cl] = 0.f; }

#pragma unroll
        for (int k = 0; 2 * k <= i + 1; ++k) {
            const int k2 = i + 1 - k;
            if (k2 == k) {
                aA[k] = aA[k] + rA * aA[k];
                aB[k] = aB[k] + rB * aB[k];
            } else {
                const float ta = aA[k], tb = aB[k];
                aA[k]  = fmaf(rA, aA[k2], aA[k]);
                aA[k2] = fmaf(rA, ta,    aA[k2]);
                aB[k]  = fmaf(rB, aB[k2], aB[k]);
                aB[k2] = fmaf(rB, tb,    aB[k2]);
            }
        }
    }

    // ---- FIR + embed, one set at a time (reuse window registers) ----
    __syncwarp();
    const float alpha = __ldg(alpha_p);

#pragma unroll
    for (int set = 0; set < 2; ++set) {
        const int   fr = set ? frB : frA;
        const float* Pp = set ? PB : PA;
        const float* ap = set ? aB : aA;
        const float sgn  = 2.f * (float)__ldg(&bits[fr]) - 1.f;
        const float coef = alpha * sgn;

        float xf[32];   // X[jb-12 .. jb+19]
        {
            const float4* W = (const float4*)(Pp + jb);   // = &P[12 + jb - 12]
#pragma unroll
            for (int k = 0; k < 8; ++k) {
                const float4 v = W[k];
                xf[4*k]=v.x; xf[4*k+1]=v.y; xf[4*k+2]=v.z; xf[4*k+3]=v.w;
            }
        }

        float o[20];
#pragma unroll
        for (int c = 0; c < 20; ++c) {
            float acc = ap[0] * xf[12 + c];
#pragma unroll
            for (int k = 1; k <= ORDER; ++k)
                acc = fmaf(ap[k], xf[12 + c - k], acc);
            o[c] = fmaf(coef, acc, xf[12 + c]);
        }

        float4* d4 = (float4*)(out + (long long)fr * FRAME + jb);
#pragma unroll
        for (int k = 0; k < 5; ++k)
            d4[k] = make_float4(o[4*k], o[4*k+1], o[4*k+2], o[4*k+3]);
    }
}

} // namespace

extern "C" void kernel_launch(void* const* d_in, const int* in_sizes, int n_in,
                              void* d_out, int out_size)
{
    const int*   bits  = (const int*)  d_in[0];
    const float* pcm   = (const float*)d_in[1];
    const float* alpha = (const float*)d_in[2];
    float*       out   = (float*)d_out;

    const int grid = NFRAMES / (WPB * 8);   // 960 blocks
    burg_residual_kernel<<<grid, THREADS>>>(bits, pcm, alpha, out);
}